// round 3
// baseline (speedup 1.0000x reference)
#include <cuda_runtime.h>
#include <cstdint>
#include <cstddef>

#define N_NODES 8192
#define FEAT    256
#define BM      64
#define BK      32
#define NTILES  (N_NODES / BK)   // 256
#define THREADS 256

// Scratch (no runtime allocation allowed)
__device__ float  d_H[N_NODES * FEAT];   // h = input @ W   (8 MB)
__device__ float4 d_G1[N_NODES];         // (s1, exp(s1), exp(0.2 s1), 0)
__device__ float4 d_G2[N_NODES];         // (s2, exp(s2), exp(0.2 s2), 0)

// ---------------------------------------------------------------------------
// Kernel 1: h = X @ W   (fp32 exact, 8192x256x256 — tiny)
// ---------------------------------------------------------------------------
__global__ __launch_bounds__(256) void gemm_h_kernel(const float* __restrict__ X,
                                                     const float* __restrict__ W) {
    __shared__ float Xs[64][16];
    __shared__ float Ws[16][64];
    const int t  = threadIdx.x;
    const int tx = t & 15, ty = t >> 4;
    const int i0 = blockIdx.y * 64, j0 = blockIdx.x * 64;
    float acc[4][4] = {};
    for (int k0 = 0; k0 < FEAT; k0 += 16) {
        {
            int r = t >> 2, kq = (t & 3) * 4;
            *(float4*)&Xs[r][kq] = *(const float4*)(X + (size_t)(i0 + r) * FEAT + k0 + kq);
            int kk = t >> 4, jq = (t & 15) * 4;
            *(float4*)&Ws[kk][jq] = *(const float4*)(W + (size_t)(k0 + kk) * FEAT + j0 + jq);
        }
        __syncthreads();
#pragma unroll
        for (int k = 0; k < 16; k++) {
            float xv[4], wv[4];
#pragma unroll
            for (int p = 0; p < 4; p++) xv[p] = Xs[ty * 4 + p][k];
#pragma unroll
            for (int q = 0; q < 4; q++) wv[q] = Ws[k][tx * 4 + q];
#pragma unroll
            for (int p = 0; p < 4; p++)
#pragma unroll
                for (int q = 0; q < 4; q++) acc[p][q] = fmaf(xv[p], wv[q], acc[p][q]);
        }
        __syncthreads();
    }
#pragma unroll
    for (int p = 0; p < 4; p++) {
        float4 o = make_float4(acc[p][0], acc[p][1], acc[p][2], acc[p][3]);
        *(float4*)(d_H + (size_t)(i0 + ty * 4 + p) * FEAT + j0 + tx * 4) = o;
    }
}

// ---------------------------------------------------------------------------
// Kernel 2: s1/s2 + separable exp factors. One warp per row.
// ---------------------------------------------------------------------------
__global__ __launch_bounds__(256) void spack_kernel(const float* __restrict__ A) {
    const int lane = threadIdx.x & 31;
    const int wid  = threadIdx.x >> 5;
    const int row  = blockIdx.x * 8 + wid;
    const float* hr = d_H + (size_t)row * FEAT;
    float s1 = 0.f, s2 = 0.f;
#pragma unroll
    for (int q = 0; q < 2; q++) {
        int f = lane * 8 + q * 4;
        float4 hv = *(const float4*)(hr + f);
        float4 a1 = *(const float4*)(A + f);
        float4 a2 = *(const float4*)(A + FEAT + f);
        s1 += hv.x * a1.x + hv.y * a1.y + hv.z * a1.z + hv.w * a1.w;
        s2 += hv.x * a2.x + hv.y * a2.y + hv.z * a2.z + hv.w * a2.w;
    }
#pragma unroll
    for (int o = 16; o > 0; o >>= 1) {
        s1 += __shfl_xor_sync(0xffffffffu, s1, o);
        s2 += __shfl_xor_sync(0xffffffffu, s2, o);
    }
    if (lane == 0) {
        d_G1[row] = make_float4(s1, expf(s1), expf(0.2f * s1), 0.f);
        d_G2[row] = make_float4(s2, expf(s2), expf(0.2f * s2), 0.f);
    }
}

// ---------------------------------------------------------------------------
// Kernel 3: fused masked-softmax @ h, FFMA2 (f32x2) main loop,
// cp.async double-buffered h + adj tiles.
// ---------------------------------------------------------------------------
__device__ __forceinline__ void cp16(void* dst, const void* src) {
    unsigned d = (unsigned)__cvta_generic_to_shared(dst);
    asm volatile("cp.async.cg.shared.global [%0], [%1], 16;" :: "r"(d), "l"(src));
}
__device__ __forceinline__ void cp_commit() {
    asm volatile("cp.async.commit_group;" ::: "memory");
}
template <int N>
__device__ __forceinline__ void cp_wait() {
    asm volatile("cp.async.wait_group %0;" :: "n"(N) : "memory");
}
#define FFMA2(d, a, b) \
    asm volatile("fma.rn.f32x2 %0, %1, %2, %0;" : "+l"(d) : "l"(a), "l"(b))

// SMEM layout (dynamic):
//  hs   : 2 x [32][256] float = 65536 B   @ 0
//  adjs : 2 x [64][32]  int   = 16384 B   @ 65536
//  g2s  : 2 x [32]      float4=  1024 B   @ 81920
//  ws   : [64][36]      float =  9216 B   @ 82944   (36-pad: 16B-aligned rows, conflict-free STS)
//  zsh  : [64]          float =   256 B   @ 92160
#define SMEM_BYTES 92416

__global__ __launch_bounds__(THREADS, 1) void gat_main_kernel(const int* __restrict__ ADJ,
                                                              float* __restrict__ OUT) {
    extern __shared__ char smbase[];
    float*  hs   = (float*)(smbase);
    int*    adjs = (int*)(smbase + 65536);
    float4* g2s  = (float4*)(smbase + 81920);
    float*  ws   = (float*)(smbase + 82944);
    float*  zsh  = (float*)(smbase + 92160);

    const int t    = threadIdx.x;
    const int lane = t & 31, wid = t >> 5;
    const int i0   = blockIdx.x * BM;
    const int R0   = wid * 8;           // 8 output rows per warp
    const int wr   = t >> 2;            // w-gen: my row (0..63)
    const int wk0  = (t & 3) * 8;       // w-gen: my k-octet

    const float4 myg1 = d_G1[i0 + wr];  // (s1, E1, F1, -)

    unsigned long long acc[8][4];       // 8 rows x 4 f32x2 pairs = 8x8 fp32 cols
#pragma unroll
    for (int p = 0; p < 8; p++)
#pragma unroll
        for (int q = 0; q < 4; q++) acc[p][q] = 0ULL;
    float zacc = 0.f;

    auto load_tile = [&](int tt, int buf) {
        const int j0 = tt * BK;
        float* hdst = hs + buf * (32 * 256);
#pragma unroll
        for (int m = 0; m < 8; m++) {
            int e  = t + 256 * m;
            int kr = e >> 6;
            int fc = (e & 63) << 2;
            cp16(hdst + kr * 256 + fc, d_H + (size_t)(j0 + kr) * FEAT + fc);
        }
        int* adst = adjs + buf * (64 * 32);
#pragma unroll
        for (int m = 0; m < 2; m++) {
            int e  = t + 256 * m;
            int r  = e >> 3;
            int kq = (e & 7) << 2;
            cp16(adst + r * 32 + kq, ADJ + (size_t)(i0 + r) * N_NODES + j0 + kq);
        }
        if (t < 32) cp16(&g2s[buf * 32 + t], &d_G2[j0 + t]);
    };

    load_tile(0, 0);
    cp_commit();

    for (int tt = 0; tt < NTILES; ++tt) {
        const int cur = tt & 1;
        if (tt + 1 < NTILES) {
            load_tile(tt + 1, cur ^ 1);
            cp_commit();
            cp_wait<1>();   // tile tt arrived
        } else {
            cp_wait<0>();
        }
        __syncthreads();

        // ---- w generation: w = adj ? (x>=0 ? E1*E2 : F1*F2) : 0 ----
        {
            const int* arow = adjs + cur * (64 * 32) + wr * 32 + wk0;
            int4 a0 = *(const int4*)(arow);
            int4 a1 = *(const int4*)(arow + 4);
            int am[8] = {a0.x, a0.y, a0.z, a0.w, a1.x, a1.y, a1.z, a1.w};
            float* wrow = ws + wr * 36 + wk0;
            const float4* g2b = g2s + cur * 32 + wk0;
#pragma unroll
            for (int m = 0; m < 8; m++) {
                float4 g = g2b[m];                 // (s2, E2, F2, -)
                float x  = myg1.x + g.x;
                float w  = (x >= 0.f ? myg1.y : myg1.z) * (x >= 0.f ? g.y : g.z);
                wrow[m]  = (am[m] != 0) ? w : 0.f;
            }
        }
        __syncthreads();

        // ---- main FMA loop (f32x2) ----
        const float* hb = hs + cur * (32 * 256);
#pragma unroll 2
        for (int k4 = 0; k4 < 8; k4++) {
            float4 wv[8];
#pragma unroll
            for (int p = 0; p < 8; p++)
                wv[p] = *(const float4*)(ws + (R0 + p) * 36 + k4 * 4);  // broadcast
#pragma unroll
            for (int kk = 0; kk < 4; kk++) {
                const int k = k4 * 4 + kk;
                ulonglong2 h0 = *(const ulonglong2*)(hb + k * 256 + lane * 4);
                ulonglong2 h1 = *(const ulonglong2*)(hb + k * 256 + 128 + lane * 4);
#pragma unroll
                for (int p = 0; p < 8; p++) {
                    float wsc = (kk == 0) ? wv[p].x : (kk == 1) ? wv[p].y
                              : (kk == 2) ? wv[p].z : wv[p].w;
                    unsigned long long w2;
                    asm("mov.b64 %0, {%1, %1};" : "=l"(w2) : "f"(wsc));
                    FFMA2(acc[p][0], w2, h0.x);
                    FFMA2(acc[p][1], w2, h0.y);
                    FFMA2(acc[p][2], w2, h1.x);
                    FFMA2(acc[p][3], w2, h1.y);
                }
            }
        }
        // ---- Z accumulation (thread t < 64 owns row t) ----
        if (t < 64) {
            const float* zr = ws + t * 36;
#pragma unroll
            for (int k4 = 0; k4 < 8; k4++) {
                float4 v = *(const float4*)(zr + k4 * 4);
                zacc += (v.x + v.y) + (v.z + v.w);
            }
        }
        __syncthreads();
    }

    if (t < 64) zsh[t] = zacc;
    __syncthreads();

    // ---- epilogue: divide by Z, elu, store ----
#pragma unroll
    for (int p = 0; p < 8; p++) {
        const float rz = 1.0f / zsh[R0 + p];
        float v[8];
#pragma unroll
        for (int q = 0; q < 4; q++) {
            float lo, hi;
            asm("mov.b64 {%0, %1}, %2;" : "=f"(lo), "=f"(hi) : "l"(acc[p][q]));
            v[2 * q] = lo; v[2 * q + 1] = hi;
        }
#pragma unroll
        for (int e = 0; e < 8; e++) {
            float x = v[e] * rz;
            v[e] = (x > 0.f) ? x : expm1f(x);
        }
        float* orow = OUT + (size_t)(i0 + R0 + p) * FEAT;
        *(float4*)(orow + lane * 4)       = make_float4(v[0], v[1], v[2], v[3]);
        *(float4*)(orow + 128 + lane * 4) = make_float4(v[4], v[5], v[6], v[7]);
    }
}

// ---------------------------------------------------------------------------
extern "C" void kernel_launch(void* const* d_in, const int* in_sizes, int n_in,
                              void* d_out, int out_size) {
    (void)in_sizes; (void)n_in; (void)out_size;
    const float* X   = (const float*)d_in[0];   // input [8192,256] f32
    const int*   ADJ = (const int*)d_in[1];     // adj   [8192,8192] i32
    const float* W   = (const float*)d_in[2];   // W     [256,256] f32
    const float* A   = (const float*)d_in[3];   // a     [512,1]  f32
    float* OUT = (float*)d_out;                 // [8192,256] f32

    gemm_h_kernel<<<dim3(4, 128), 256>>>(X, W);
    spack_kernel<<<N_NODES / 8, 256>>>(A);
    cudaFuncSetAttribute(gat_main_kernel,
                         cudaFuncAttributeMaxDynamicSharedMemorySize, SMEM_BYTES);
    gat_main_kernel<<<N_NODES / BM, THREADS, SMEM_BYTES>>>(ADJ, OUT);
}

// round 4
// speedup vs baseline: 1.0025x; 1.0025x over previous
#include <cuda_runtime.h>
#include <cstdint>
#include <cstddef>

#define N_NODES 8192
#define FEAT    256
#define BM      64
#define BK      32
#define NTILES  (N_NODES / BK)   // 256
#define THREADS 256

// Scratch (no runtime allocation allowed)
__device__ float  d_H[N_NODES * FEAT];   // h = input @ W   (8 MB)
__device__ float4 d_G1[N_NODES];         // (s1, exp(s1), exp(0.2 s1), 0)
__device__ float4 d_G2[N_NODES];         // (s2, exp(s2), exp(0.2 s2), 0)

// ---------------------------------------------------------------------------
// Kernel 1: h = X @ W   (fp32 exact, 8192x256x256 — tiny)
// ---------------------------------------------------------------------------
__global__ __launch_bounds__(256) void gemm_h_kernel(const float* __restrict__ X,
                                                     const float* __restrict__ W) {
    __shared__ float Xs[64][16];
    __shared__ float Ws[16][64];
    const int t  = threadIdx.x;
    const int tx = t & 15, ty = t >> 4;
    const int i0 = blockIdx.y * 64, j0 = blockIdx.x * 64;
    float acc[4][4] = {};
    for (int k0 = 0; k0 < FEAT; k0 += 16) {
        {
            int r = t >> 2, kq = (t & 3) * 4;
            *(float4*)&Xs[r][kq] = *(const float4*)(X + (size_t)(i0 + r) * FEAT + k0 + kq);
            int kk = t >> 4, jq = (t & 15) * 4;
            *(float4*)&Ws[kk][jq] = *(const float4*)(W + (size_t)(k0 + kk) * FEAT + j0 + jq);
        }
        __syncthreads();
#pragma unroll
        for (int k = 0; k < 16; k++) {
            float xv[4], wv[4];
#pragma unroll
            for (int p = 0; p < 4; p++) xv[p] = Xs[ty * 4 + p][k];
#pragma unroll
            for (int q = 0; q < 4; q++) wv[q] = Ws[k][tx * 4 + q];
#pragma unroll
            for (int p = 0; p < 4; p++)
#pragma unroll
                for (int q = 0; q < 4; q++) acc[p][q] = fmaf(xv[p], wv[q], acc[p][q]);
        }
        __syncthreads();
    }
#pragma unroll
    for (int p = 0; p < 4; p++) {
        float4 o = make_float4(acc[p][0], acc[p][1], acc[p][2], acc[p][3]);
        *(float4*)(d_H + (size_t)(i0 + ty * 4 + p) * FEAT + j0 + tx * 4) = o;
    }
}

// ---------------------------------------------------------------------------
// Kernel 2: s1/s2 + separable exp factors. One warp per row.
// ---------------------------------------------------------------------------
__global__ __launch_bounds__(256) void spack_kernel(const float* __restrict__ A) {
    const int lane = threadIdx.x & 31;
    const int wid  = threadIdx.x >> 5;
    const int row  = blockIdx.x * 8 + wid;
    const float* hr = d_H + (size_t)row * FEAT;
    float s1 = 0.f, s2 = 0.f;
#pragma unroll
    for (int q = 0; q < 2; q++) {
        int f = lane * 8 + q * 4;
        float4 hv = *(const float4*)(hr + f);
        float4 a1 = *(const float4*)(A + f);
        float4 a2 = *(const float4*)(A + FEAT + f);
        s1 += hv.x * a1.x + hv.y * a1.y + hv.z * a1.z + hv.w * a1.w;
        s2 += hv.x * a2.x + hv.y * a2.y + hv.z * a2.z + hv.w * a2.w;
    }
#pragma unroll
    for (int o = 16; o > 0; o >>= 1) {
        s1 += __shfl_xor_sync(0xffffffffu, s1, o);
        s2 += __shfl_xor_sync(0xffffffffu, s2, o);
    }
    if (lane == 0) {
        d_G1[row] = make_float4(s1, expf(s1), expf(0.2f * s1), 0.f);
        d_G2[row] = make_float4(s2, expf(s2), expf(0.2f * s2), 0.f);
    }
}

// ---------------------------------------------------------------------------
// Kernel 3: fused masked-softmax @ h, FFMA2 (f32x2) main loop,
// cp.async double-buffered h + adj tiles.
// ---------------------------------------------------------------------------
__device__ __forceinline__ void cp16(void* dst, const void* src) {
    unsigned d = (unsigned)__cvta_generic_to_shared(dst);
    asm volatile("cp.async.cg.shared.global [%0], [%1], 16;" :: "r"(d), "l"(src));
}
__device__ __forceinline__ void cp_commit() {
    asm volatile("cp.async.commit_group;" ::: "memory");
}
template <int N>
__device__ __forceinline__ void cp_wait() {
    asm volatile("cp.async.wait_group %0;" :: "n"(N) : "memory");
}
#define FFMA2(d, a, b) \
    asm volatile("fma.rn.f32x2 %0, %1, %2, %0;" : "+l"(d) : "l"(a), "l"(b))

// SMEM layout (dynamic):
//  hs   : 2 x [32][256] float = 65536 B   @ 0
//  adjs : 2 x [64][32]  int   = 16384 B   @ 65536
//  g2s  : 2 x [32]      float4=  1024 B   @ 81920
//  ws   : [64][36]      float =  9216 B   @ 82944   (36-pad: 16B-aligned rows, conflict-free STS)
//  zsh  : [64]          float =   256 B   @ 92160
#define SMEM_BYTES 92416

__global__ __launch_bounds__(THREADS, 1) void gat_main_kernel(const int* __restrict__ ADJ,
                                                              float* __restrict__ OUT) {
    extern __shared__ char smbase[];
    float*  hs   = (float*)(smbase);
    int*    adjs = (int*)(smbase + 65536);
    float4* g2s  = (float4*)(smbase + 81920);
    float*  ws   = (float*)(smbase + 82944);
    float*  zsh  = (float*)(smbase + 92160);

    const int t    = threadIdx.x;
    const int lane = t & 31, wid = t >> 5;
    const int i0   = blockIdx.x * BM;
    const int R0   = wid * 8;           // 8 output rows per warp
    const int wr   = t >> 2;            // w-gen: my row (0..63)
    const int wk0  = (t & 3) * 8;       // w-gen: my k-octet

    const float4 myg1 = d_G1[i0 + wr];  // (s1, E1, F1, -)

    unsigned long long acc[8][4];       // 8 rows x 4 f32x2 pairs = 8x8 fp32 cols
#pragma unroll
    for (int p = 0; p < 8; p++)
#pragma unroll
        for (int q = 0; q < 4; q++) acc[p][q] = 0ULL;
    float zacc = 0.f;

    auto load_tile = [&](int tt, int buf) {
        const int j0 = tt * BK;
        float* hdst = hs + buf * (32 * 256);
#pragma unroll
        for (int m = 0; m < 8; m++) {
            int e  = t + 256 * m;
            int kr = e >> 6;
            int fc = (e & 63) << 2;
            cp16(hdst + kr * 256 + fc, d_H + (size_t)(j0 + kr) * FEAT + fc);
        }
        int* adst = adjs + buf * (64 * 32);
#pragma unroll
        for (int m = 0; m < 2; m++) {
            int e  = t + 256 * m;
            int r  = e >> 3;
            int kq = (e & 7) << 2;
            cp16(adst + r * 32 + kq, ADJ + (size_t)(i0 + r) * N_NODES + j0 + kq);
        }
        if (t < 32) cp16(&g2s[buf * 32 + t], &d_G2[j0 + t]);
    };

    load_tile(0, 0);
    cp_commit();

    for (int tt = 0; tt < NTILES; ++tt) {
        const int cur = tt & 1;
        if (tt + 1 < NTILES) {
            load_tile(tt + 1, cur ^ 1);
            cp_commit();
            cp_wait<1>();   // tile tt arrived
        } else {
            cp_wait<0>();
        }
        __syncthreads();

        // ---- w generation: w = adj ? (x>=0 ? E1*E2 : F1*F2) : 0 ----
        {
            const int* arow = adjs + cur * (64 * 32) + wr * 32 + wk0;
            int4 a0 = *(const int4*)(arow);
            int4 a1 = *(const int4*)(arow + 4);
            int am[8] = {a0.x, a0.y, a0.z, a0.w, a1.x, a1.y, a1.z, a1.w};
            float* wrow = ws + wr * 36 + wk0;
            const float4* g2b = g2s + cur * 32 + wk0;
#pragma unroll
            for (int m = 0; m < 8; m++) {
                float4 g = g2b[m];                 // (s2, E2, F2, -)
                float x  = myg1.x + g.x;
                float w  = (x >= 0.f ? myg1.y : myg1.z) * (x >= 0.f ? g.y : g.z);
                wrow[m]  = (am[m] != 0) ? w : 0.f;
            }
        }
        __syncthreads();

        // ---- main FMA loop (f32x2) ----
        const float* hb = hs + cur * (32 * 256);
#pragma unroll 2
        for (int k4 = 0; k4 < 8; k4++) {
            float4 wv[8];
#pragma unroll
            for (int p = 0; p < 8; p++)
                wv[p] = *(const float4*)(ws + (R0 + p) * 36 + k4 * 4);  // broadcast
#pragma unroll
            for (int kk = 0; kk < 4; kk++) {
                const int k = k4 * 4 + kk;
                ulonglong2 h0 = *(const ulonglong2*)(hb + k * 256 + lane * 4);
                ulonglong2 h1 = *(const ulonglong2*)(hb + k * 256 + 128 + lane * 4);
#pragma unroll
                for (int p = 0; p < 8; p++) {
                    float wsc = (kk == 0) ? wv[p].x : (kk == 1) ? wv[p].y
                              : (kk == 2) ? wv[p].z : wv[p].w;
                    unsigned long long w2;
                    asm("mov.b64 %0, {%1, %1};" : "=l"(w2) : "f"(wsc));
                    FFMA2(acc[p][0], w2, h0.x);
                    FFMA2(acc[p][1], w2, h0.y);
                    FFMA2(acc[p][2], w2, h1.x);
                    FFMA2(acc[p][3], w2, h1.y);
                }
            }
        }
        // ---- Z accumulation (thread t < 64 owns row t) ----
        if (t < 64) {
            const float* zr = ws + t * 36;
#pragma unroll
            for (int k4 = 0; k4 < 8; k4++) {
                float4 v = *(const float4*)(zr + k4 * 4);
                zacc += (v.x + v.y) + (v.z + v.w);
            }
        }
        __syncthreads();
    }

    if (t < 64) zsh[t] = zacc;
    __syncthreads();

    // ---- epilogue: divide by Z, elu, store ----
#pragma unroll
    for (int p = 0; p < 8; p++) {
        const float rz = 1.0f / zsh[R0 + p];
        float v[8];
#pragma unroll
        for (int q = 0; q < 4; q++) {
            float lo, hi;
            asm("mov.b64 {%0, %1}, %2;" : "=f"(lo), "=f"(hi) : "l"(acc[p][q]));
            v[2 * q] = lo; v[2 * q + 1] = hi;
        }
#pragma unroll
        for (int e = 0; e < 8; e++) {
            float x = v[e] * rz;
            v[e] = (x > 0.f) ? x : expm1f(x);
        }
        float* orow = OUT + (size_t)(i0 + R0 + p) * FEAT;
        *(float4*)(orow + lane * 4)       = make_float4(v[0], v[1], v[2], v[3]);
        *(float4*)(orow + 128 + lane * 4) = make_float4(v[4], v[5], v[6], v[7]);
    }
}

// ---------------------------------------------------------------------------
extern "C" void kernel_launch(void* const* d_in, const int* in_sizes, int n_in,
                              void* d_out, int out_size) {
    (void)in_sizes; (void)n_in; (void)out_size;
    const float* X   = (const float*)d_in[0];   // input [8192,256] f32
    const int*   ADJ = (const int*)d_in[1];     // adj   [8192,8192] i32
    const float* W   = (const float*)d_in[2];   // W     [256,256] f32
    const float* A   = (const float*)d_in[3];   // a     [512,1]  f32
    float* OUT = (float*)d_out;                 // [8192,256] f32

    gemm_h_kernel<<<dim3(4, 128), 256>>>(X, W);
    spack_kernel<<<N_NODES / 8, 256>>>(A);
    cudaFuncSetAttribute(gat_main_kernel,
                         cudaFuncAttributeMaxDynamicSharedMemorySize, SMEM_BYTES);
    gat_main_kernel<<<N_NODES / BM, THREADS, SMEM_BYTES>>>(ADJ, OUT);
}

// round 5
// speedup vs baseline: 1.0040x; 1.0015x over previous
#include <cuda_runtime.h>
#include <cstdint>
#include <cstddef>

#define N_NODES 8192
#define FEAT    256
#define BM      64
#define BK      32
#define NTILES  (N_NODES / BK)   // 256
#define THREADS 256

// Scratch (no runtime allocation allowed)
__device__ float  d_H[N_NODES * FEAT];   // h = input @ W   (8 MB)
__device__ float4 d_G1[N_NODES];         // (s1, exp(s1), exp(0.2 s1), 0)
__device__ float4 d_G2[N_NODES];         // (s2, exp(s2), exp(0.2 s2), 0)

// ---------------------------------------------------------------------------
// Kernel 1: h = X @ W   (fp32 exact, 8192x256x256 — tiny)
// ---------------------------------------------------------------------------
__global__ __launch_bounds__(256) void gemm_h_kernel(const float* __restrict__ X,
                                                     const float* __restrict__ W) {
    __shared__ float Xs[64][16];
    __shared__ float Ws[16][64];
    const int t  = threadIdx.x;
    const int tx = t & 15, ty = t >> 4;
    const int i0 = blockIdx.y * 64, j0 = blockIdx.x * 64;
    float acc[4][4] = {};
    for (int k0 = 0; k0 < FEAT; k0 += 16) {
        {
            int r = t >> 2, kq = (t & 3) * 4;
            *(float4*)&Xs[r][kq] = *(const float4*)(X + (size_t)(i0 + r) * FEAT + k0 + kq);
            int kk = t >> 4, jq = (t & 15) * 4;
            *(float4*)&Ws[kk][jq] = *(const float4*)(W + (size_t)(k0 + kk) * FEAT + j0 + jq);
        }
        __syncthreads();
#pragma unroll
        for (int k = 0; k < 16; k++) {
            float xv[4], wv[4];
#pragma unroll
            for (int p = 0; p < 4; p++) xv[p] = Xs[ty * 4 + p][k];
#pragma unroll
            for (int q = 0; q < 4; q++) wv[q] = Ws[k][tx * 4 + q];
#pragma unroll
            for (int p = 0; p < 4; p++)
#pragma unroll
                for (int q = 0; q < 4; q++) acc[p][q] = fmaf(xv[p], wv[q], acc[p][q]);
        }
        __syncthreads();
    }
#pragma unroll
    for (int p = 0; p < 4; p++) {
        float4 o = make_float4(acc[p][0], acc[p][1], acc[p][2], acc[p][3]);
        *(float4*)(d_H + (size_t)(i0 + ty * 4 + p) * FEAT + j0 + tx * 4) = o;
    }
}

// ---------------------------------------------------------------------------
// Kernel 2: s1/s2 + separable exp factors. One warp per row.
// ---------------------------------------------------------------------------
__global__ __launch_bounds__(256) void spack_kernel(const float* __restrict__ A) {
    const int lane = threadIdx.x & 31;
    const int wid  = threadIdx.x >> 5;
    const int row  = blockIdx.x * 8 + wid;
    const float* hr = d_H + (size_t)row * FEAT;
    float s1 = 0.f, s2 = 0.f;
#pragma unroll
    for (int q = 0; q < 2; q++) {
        int f = lane * 8 + q * 4;
        float4 hv = *(const float4*)(hr + f);
        float4 a1 = *(const float4*)(A + f);
        float4 a2 = *(const float4*)(A + FEAT + f);
        s1 += hv.x * a1.x + hv.y * a1.y + hv.z * a1.z + hv.w * a1.w;
        s2 += hv.x * a2.x + hv.y * a2.y + hv.z * a2.z + hv.w * a2.w;
    }
#pragma unroll
    for (int o = 16; o > 0; o >>= 1) {
        s1 += __shfl_xor_sync(0xffffffffu, s1, o);
        s2 += __shfl_xor_sync(0xffffffffu, s2, o);
    }
    if (lane == 0) {
        d_G1[row] = make_float4(s1, expf(s1), expf(0.2f * s1), 0.f);
        d_G2[row] = make_float4(s2, expf(s2), expf(0.2f * s2), 0.f);
    }
}

// ---------------------------------------------------------------------------
// Kernel 3: fused masked-softmax @ h, FFMA2 (f32x2) main loop,
// cp.async double-buffered h + adj tiles.
// ---------------------------------------------------------------------------
__device__ __forceinline__ void cp16(void* dst, const void* src) {
    unsigned d = (unsigned)__cvta_generic_to_shared(dst);
    asm volatile("cp.async.cg.shared.global [%0], [%1], 16;" :: "r"(d), "l"(src));
}
__device__ __forceinline__ void cp_commit() {
    asm volatile("cp.async.commit_group;" ::: "memory");
}
template <int N>
__device__ __forceinline__ void cp_wait() {
    asm volatile("cp.async.wait_group %0;" :: "n"(N) : "memory");
}
#define FFMA2(d, a, b) \
    asm volatile("fma.rn.f32x2 %0, %1, %2, %0;" : "+l"(d) : "l"(a), "l"(b))

// SMEM layout (dynamic):
//  hs   : 2 x [32][256] float = 65536 B   @ 0
//  adjs : 2 x [64][32]  int   = 16384 B   @ 65536
//  g2s  : 2 x [32]      float4=  1024 B   @ 81920
//  ws   : [64][36]      float =  9216 B   @ 82944   (36-pad: 16B-aligned rows, conflict-free STS)
//  zsh  : [64]          float =   256 B   @ 92160
#define SMEM_BYTES 92416

__global__ __launch_bounds__(THREADS, 1) void gat_main_kernel(const int* __restrict__ ADJ,
                                                              float* __restrict__ OUT) {
    extern __shared__ char smbase[];
    float*  hs   = (float*)(smbase);
    int*    adjs = (int*)(smbase + 65536);
    float4* g2s  = (float4*)(smbase + 81920);
    float*  ws   = (float*)(smbase + 82944);
    float*  zsh  = (float*)(smbase + 92160);

    const int t    = threadIdx.x;
    const int lane = t & 31, wid = t >> 5;
    const int i0   = blockIdx.x * BM;
    const int R0   = wid * 8;           // 8 output rows per warp
    const int wr   = t >> 2;            // w-gen: my row (0..63)
    const int wk0  = (t & 3) * 8;       // w-gen: my k-octet

    const float4 myg1 = d_G1[i0 + wr];  // (s1, E1, F1, -)

    unsigned long long acc[8][4];       // 8 rows x 4 f32x2 pairs = 8x8 fp32 cols
#pragma unroll
    for (int p = 0; p < 8; p++)
#pragma unroll
        for (int q = 0; q < 4; q++) acc[p][q] = 0ULL;
    float zacc = 0.f;

    auto load_tile = [&](int tt, int buf) {
        const int j0 = tt * BK;
        float* hdst = hs + buf * (32 * 256);
#pragma unroll
        for (int m = 0; m < 8; m++) {
            int e  = t + 256 * m;
            int kr = e >> 6;
            int fc = (e & 63) << 2;
            cp16(hdst + kr * 256 + fc, d_H + (size_t)(j0 + kr) * FEAT + fc);
        }
        int* adst = adjs + buf * (64 * 32);
#pragma unroll
        for (int m = 0; m < 2; m++) {
            int e  = t + 256 * m;
            int r  = e >> 3;
            int kq = (e & 7) << 2;
            cp16(adst + r * 32 + kq, ADJ + (size_t)(i0 + r) * N_NODES + j0 + kq);
        }
        if (t < 32) cp16(&g2s[buf * 32 + t], &d_G2[j0 + t]);
    };

    load_tile(0, 0);
    cp_commit();

    for (int tt = 0; tt < NTILES; ++tt) {
        const int cur = tt & 1;
        if (tt + 1 < NTILES) {
            load_tile(tt + 1, cur ^ 1);
            cp_commit();
            cp_wait<1>();   // tile tt arrived
        } else {
            cp_wait<0>();
        }
        __syncthreads();

        // ---- w generation: w = adj ? (x>=0 ? E1*E2 : F1*F2) : 0 ----
        {
            const int* arow = adjs + cur * (64 * 32) + wr * 32 + wk0;
            int4 a0 = *(const int4*)(arow);
            int4 a1 = *(const int4*)(arow + 4);
            int am[8] = {a0.x, a0.y, a0.z, a0.w, a1.x, a1.y, a1.z, a1.w};
            float* wrow = ws + wr * 36 + wk0;
            const float4* g2b = g2s + cur * 32 + wk0;
#pragma unroll
            for (int m = 0; m < 8; m++) {
                float4 g = g2b[m];                 // (s2, E2, F2, -)
                float x  = myg1.x + g.x;
                float w  = (x >= 0.f ? myg1.y : myg1.z) * (x >= 0.f ? g.y : g.z);
                wrow[m]  = (am[m] != 0) ? w : 0.f;
            }
        }
        __syncthreads();

        // ---- main FMA loop (f32x2) ----
        const float* hb = hs + cur * (32 * 256);
#pragma unroll 2
        for (int k4 = 0; k4 < 8; k4++) {
            float4 wv[8];
#pragma unroll
            for (int p = 0; p < 8; p++)
                wv[p] = *(const float4*)(ws + (R0 + p) * 36 + k4 * 4);  // broadcast
#pragma unroll
            for (int kk = 0; kk < 4; kk++) {
                const int k = k4 * 4 + kk;
                ulonglong2 h0 = *(const ulonglong2*)(hb + k * 256 + lane * 4);
                ulonglong2 h1 = *(const ulonglong2*)(hb + k * 256 + 128 + lane * 4);
#pragma unroll
                for (int p = 0; p < 8; p++) {
                    float wsc = (kk == 0) ? wv[p].x : (kk == 1) ? wv[p].y
                              : (kk == 2) ? wv[p].z : wv[p].w;
                    unsigned long long w2;
                    asm("mov.b64 %0, {%1, %1};" : "=l"(w2) : "f"(wsc));
                    FFMA2(acc[p][0], w2, h0.x);
                    FFMA2(acc[p][1], w2, h0.y);
                    FFMA2(acc[p][2], w2, h1.x);
                    FFMA2(acc[p][3], w2, h1.y);
                }
            }
        }
        // ---- Z accumulation (thread t < 64 owns row t) ----
        if (t < 64) {
            const float* zr = ws + t * 36;
#pragma unroll
            for (int k4 = 0; k4 < 8; k4++) {
                float4 v = *(const float4*)(zr + k4 * 4);
                zacc += (v.x + v.y) + (v.z + v.w);
            }
        }
        __syncthreads();
    }

    if (t < 64) zsh[t] = zacc;
    __syncthreads();

    // ---- epilogue: divide by Z, elu, store ----
#pragma unroll
    for (int p = 0; p < 8; p++) {
        const float rz = 1.0f / zsh[R0 + p];
        float v[8];
#pragma unroll
        for (int q = 0; q < 4; q++) {
            float lo, hi;
            asm("mov.b64 {%0, %1}, %2;" : "=f"(lo), "=f"(hi) : "l"(acc[p][q]));
            v[2 * q] = lo; v[2 * q + 1] = hi;
        }
#pragma unroll
        for (int e = 0; e < 8; e++) {
            float x = v[e] * rz;
            v[e] = (x > 0.f) ? x : expm1f(x);
        }
        float* orow = OUT + (size_t)(i0 + R0 + p) * FEAT;
        *(float4*)(orow + lane * 4)       = make_float4(v[0], v[1], v[2], v[3]);
        *(float4*)(orow + 128 + lane * 4) = make_float4(v[4], v[5], v[6], v[7]);
    }
}

// ---------------------------------------------------------------------------
extern "C" void kernel_launch(void* const* d_in, const int* in_sizes, int n_in,
                              void* d_out, int out_size) {
    (void)in_sizes; (void)n_in; (void)out_size;
    const float* X   = (const float*)d_in[0];   // input [8192,256] f32
    const int*   ADJ = (const int*)d_in[1];     // adj   [8192,8192] i32
    const float* W   = (const float*)d_in[2];   // W     [256,256] f32
    const float* A   = (const float*)d_in[3];   // a     [512,1]  f32
    float* OUT = (float*)d_out;                 // [8192,256] f32

    gemm_h_kernel<<<dim3(4, 128), 256>>>(X, W);
    spack_kernel<<<N_NODES / 8, 256>>>(A);
    cudaFuncSetAttribute(gat_main_kernel,
                         cudaFuncAttributeMaxDynamicSharedMemorySize, SMEM_BYTES);
    gat_main_kernel<<<N_NODES / BM, THREADS, SMEM_BYTES>>>(ADJ, OUT);
}

// round 9
// speedup vs baseline: 3.2710x; 3.2581x over previous
#include <cuda_runtime.h>
#include <cuda_fp16.h>
#include <cstdint>
#include <cstddef>

#define N_NODES 8192
#define FEAT    256
#define BM      64           // output rows per CTA (main kernel)
#define BK      32           // k-tile (nodes)
#define NTILES  (N_NODES / BK)   // 256
#define THREADS 256

// Scratch (no runtime allocation allowed)
__device__ float  d_H [N_NODES * FEAT];  // h = X@W (fp32 exact, for spack)
__device__ __half d_Hh[N_NODES * FEAT];  // h in fp16 (MMA B operand), row-major
__device__ float4 d_G1[N_NODES];         // (s1, exp(s1), exp(0.2 s1), 0)
__device__ float4 d_G2[N_NODES];         // (s2, exp(s2), exp(0.2 s2), 0)

// ---------------------------------------------------------------------------
// helpers
// ---------------------------------------------------------------------------
__device__ __forceinline__ uint32_t smem_u32(const void* p) {
    uint32_t a;
    asm("{ .reg .u64 t; cvta.to.shared.u64 t, %1; cvt.u32.u64 %0, t; }" : "=r"(a) : "l"(p));
    return a;
}
__device__ __forceinline__ void cp16(void* dst, const void* src) {
    unsigned d = (unsigned)__cvta_generic_to_shared(dst);
    asm volatile("cp.async.cg.shared.global [%0], [%1], 16;" :: "r"(d), "l"(src));
}
__device__ __forceinline__ void cp_commit() {
    asm volatile("cp.async.commit_group;" ::: "memory");
}
template <int N>
__device__ __forceinline__ void cp_wait() {
    asm volatile("cp.async.wait_group %0;" :: "n"(N) : "memory");
}
#define LDSM4(R, addr)                                                          \
    asm volatile("ldmatrix.sync.aligned.m8n8.x4.shared.b16 {%0,%1,%2,%3}, [%4];" \
                 : "=r"((R)[0]), "=r"((R)[1]), "=r"((R)[2]), "=r"((R)[3])       \
                 : "r"(addr))
#define LDSM4T(R, addr)                                                               \
    asm volatile("ldmatrix.sync.aligned.m8n8.x4.trans.shared.b16 {%0,%1,%2,%3}, [%4];" \
                 : "=r"((R)[0]), "=r"((R)[1]), "=r"((R)[2]), "=r"((R)[3])             \
                 : "r"(addr))
#define MMA16816(D, A, B0, B1)                                                  \
    asm volatile("mma.sync.aligned.m16n8k16.row.col.f32.f16.f16.f32 "           \
                 "{%0,%1,%2,%3}, {%4,%5,%6,%7}, {%8,%9}, {%0,%1,%2,%3};"        \
                 : "+f"((D)[0]), "+f"((D)[1]), "+f"((D)[2]), "+f"((D)[3])       \
                 : "r"((A)[0]), "r"((A)[1]), "r"((A)[2]), "r"((A)[3]),          \
                   "r"(B0), "r"(B1))

// ---------------------------------------------------------------------------
// Kernel 1: h = X @ W (fp32 exact) ; also d_Hh = fp16(h) row-major
// ---------------------------------------------------------------------------
__global__ __launch_bounds__(256) void gemm_h_kernel(const float* __restrict__ X,
                                                     const float* __restrict__ W) {
    __shared__ float Xs[64][16];
    __shared__ float Ws[16][64];
    const int t  = threadIdx.x;
    const int tx = t & 15, ty = t >> 4;
    const int i0 = blockIdx.y * 64, j0 = blockIdx.x * 64;
    float acc[4][4] = {};
    for (int k0 = 0; k0 < FEAT; k0 += 16) {
        {
            int r = t >> 2, kq = (t & 3) * 4;
            *(float4*)&Xs[r][kq] = *(const float4*)(X + (size_t)(i0 + r) * FEAT + k0 + kq);
            int kk = t >> 4, jq = (t & 15) * 4;
            *(float4*)&Ws[kk][jq] = *(const float4*)(W + (size_t)(k0 + kk) * FEAT + j0 + jq);
        }
        __syncthreads();
#pragma unroll
        for (int k = 0; k < 16; k++) {
            float xv[4], wv[4];
#pragma unroll
            for (int p = 0; p < 4; p++) xv[p] = Xs[ty * 4 + p][k];
#pragma unroll
            for (int q = 0; q < 4; q++) wv[q] = Ws[k][tx * 4 + q];
#pragma unroll
            for (int p = 0; p < 4; p++)
#pragma unroll
                for (int q = 0; q < 4; q++) acc[p][q] = fmaf(xv[p], wv[q], acc[p][q]);
        }
        __syncthreads();
    }
#pragma unroll
    for (int p = 0; p < 4; p++) {
        float4 o = make_float4(acc[p][0], acc[p][1], acc[p][2], acc[p][3]);
        *(float4*)(d_H + (size_t)(i0 + ty * 4 + p) * FEAT + j0 + tx * 4) = o;
        __half2 h01 = __floats2half2_rn(acc[p][0], acc[p][1]);
        __half2 h23 = __floats2half2_rn(acc[p][2], acc[p][3]);
        uint2 hp;
        hp.x = *(uint32_t*)&h01;
        hp.y = *(uint32_t*)&h23;
        *(uint2*)(d_Hh + (size_t)(i0 + ty * 4 + p) * FEAT + j0 + tx * 4) = hp;
    }
}

// ---------------------------------------------------------------------------
// Kernel 2: s1/s2 + separable exp factors. One warp per row.
// ---------------------------------------------------------------------------
__global__ __launch_bounds__(256) void spack_kernel(const float* __restrict__ A) {
    const int lane = threadIdx.x & 31;
    const int wid  = threadIdx.x >> 5;
    const int row  = blockIdx.x * 8 + wid;
    const float* hr = d_H + (size_t)row * FEAT;
    float s1 = 0.f, s2 = 0.f;
#pragma unroll
    for (int q = 0; q < 2; q++) {
        int f = lane * 8 + q * 4;
        float4 hv = *(const float4*)(hr + f);
        float4 a1 = *(const float4*)(A + f);
        float4 a2 = *(const float4*)(A + FEAT + f);
        s1 += hv.x * a1.x + hv.y * a1.y + hv.z * a1.z + hv.w * a1.w;
        s2 += hv.x * a2.x + hv.y * a2.y + hv.z * a2.z + hv.w * a2.w;
    }
#pragma unroll
    for (int o = 16; o > 0; o >>= 1) {
        s1 += __shfl_xor_sync(0xffffffffu, s1, o);
        s2 += __shfl_xor_sync(0xffffffffu, s2, o);
    }
    if (lane == 0) {
        d_G1[row] = make_float4(s1, expf(s1), expf(0.2f * s1), 0.f);
        d_G2[row] = make_float4(s2, expf(s2), expf(0.2f * s2), 0.f);
    }
}

// ---------------------------------------------------------------------------
// Kernel 3: flash-style fused masked-softmax @ h, fp16 mma.sync (HMMA).
// SMEM layout (dynamic):
//   Hs   : 2 x 16384  (H tile 32(j) x 256(f) fp16, 16B-chunk XOR swizzle) @ 0
//   adjs : 2 x 8192   (adj tile 64 x 32 i32, linear)                     @ 32768
//   Ps   : 2 x 5120   (P tile 64 x 32 fp16, row pitch 40 halves = 80B)   @ 49152
//   g2s  : 2 x 512    (32 float4)                                        @ 59392
//   zsh  : 64 floats                                                     @ 60416
#define HS_OFF   0
#define HS_SZ    16384
#define ADJ_OFF  32768
#define ADJ_SZ   8192
#define PS_OFF   49152
#define PS_SZ    5120
#define G2_OFF   59392
#define ZSH_OFF  60416
#define SMEMM_BYTES 60672
#define PPITCH_B 80     // P row pitch in bytes (40 halves)

__global__ __launch_bounds__(THREADS, 1) void gat_mma_kernel(const int* __restrict__ ADJ,
                                                             float* __restrict__ OUT) {
    extern __shared__ char sm[];
    const uint32_t smb = smem_u32(sm);
    const int t    = threadIdx.x;
    const int wid  = t >> 5, lane = t & 31;
    const int i0   = blockIdx.x * BM;
    const int g    = t & 7;       // P-gen: k-quad (cols 4g..4g+3)
    const int r0   = t >> 3;      // P-gen: row base (rows r0, r0+32)
    const int wM   = wid & 1;     // warp M tile: rows wM*32 .. +31
    const int wF   = wid >> 1;    // warp F tile: cols wF*64 .. +63

    float4 g1v[2];
#pragma unroll
    for (int m = 0; m < 2; m++) g1v[m] = d_G1[i0 + r0 + 32 * m];
    float zac[2] = {0.f, 0.f};

    float acc[2][8][4];           // [mfrag][n8frag][reg]
#pragma unroll
    for (int a = 0; a < 2; a++)
#pragma unroll
        for (int b = 0; b < 8; b++)
#pragma unroll
            for (int c = 0; c < 4; c++) acc[a][b][c] = 0.f;

    auto load_tile = [&](int s, int buf) {
        const int j0 = s * BK;
        // H tile: 32 rows x 32 16B-chunks, chunk c stored at c ^ (j&7)
        char* hdst = sm + HS_OFF + buf * HS_SZ;
#pragma unroll
        for (int m = 0; m < 4; m++) {
            int e = t + 256 * m;
            int j = e >> 5, c = e & 31;
            cp16(hdst + j * 512 + ((c ^ (j & 7)) << 4),
                 d_Hh + (size_t)(j0 + j) * FEAT + c * 8);
        }
        // adj tile: 64 rows x 8 16B-chunks
        char* adst = sm + ADJ_OFF + buf * ADJ_SZ;
#pragma unroll
        for (int m = 0; m < 2; m++) {
            int e = t + 256 * m;
            int r = e >> 3, c = e & 7;
            cp16(adst + r * 128 + c * 16, ADJ + (size_t)(i0 + r) * N_NODES + j0 + c * 4);
        }
        if (t < 32) cp16(sm + G2_OFF + buf * 512 + t * 16, d_G2 + j0 + t);
    };

    load_tile(0, 0);
    cp_commit();

    // precomputed ldmatrix address pieces
    const uint32_t a_base = smb + PS_OFF +
                            (uint32_t)(wM * 32 + (lane & 15)) * PPITCH_B +
                            (uint32_t)((lane >> 4) * 8) * 2;
    const int bj_lane = lane & 15;           // row within k-half
    const int bf_off  = (lane >> 4) * 8;     // col offset within n16

    for (int s = 0; s < NTILES; ++s) {
        const int cur = s & 1;
        if (s + 1 < NTILES) {
            load_tile(s + 1, cur ^ 1);
            cp_commit();
            cp_wait<1>();      // tile s resident
        } else {
            cp_wait<0>();
        }
        __syncthreads();

        // ---- P-tile generation: w = adj ? exp(lrelu(s1+s2)) : 0 (rank-1 separable) ----
        {
            const float4* g2b = (const float4*)(sm + G2_OFF + cur * 512) + g * 4;
            float4 G[4];
#pragma unroll
            for (int j = 0; j < 4; j++) G[j] = g2b[j];
            const int4* abase = (const int4*)(sm + ADJ_OFF + cur * ADJ_SZ);
            char* pbase = sm + PS_OFF + cur * PS_SZ;
#pragma unroll
            for (int m = 0; m < 2; m++) {
                const int r = r0 + 32 * m;
                int4 av = abase[r * 8 + g];
                int msk[4] = {av.x, av.y, av.z, av.w};
                __half hw[4];
#pragma unroll
                for (int j = 0; j < 4; j++) {
                    float x = g1v[m].x + G[j].x;
                    float e = (x >= 0.f ? g1v[m].y : g1v[m].z) *
                              (x >= 0.f ? G[j].y : G[j].z);
                    e = (msk[j] != 0) ? e : 0.f;
                    hw[j] = __float2half_rn(e);
                    zac[m] += __half2float(hw[j]);   // Z from the SAME rounded w
                }
                __half2 p01 = __halves2half2(hw[0], hw[1]);
                __half2 p23 = __halves2half2(hw[2], hw[3]);
                uint2 pk;
                pk.x = *(uint32_t*)&p01;
                pk.y = *(uint32_t*)&p23;
                *(uint2*)(pbase + r * PPITCH_B + g * 8) = pk;
            }
        }
        __syncthreads();

        // ---- HMMA: acc += P[64x32] @ H[32x256]  (warp tile 32x64) ----
        {
            const uint32_t hbase = smb + HS_OFF + cur * HS_SZ;
            const uint32_t acur  = a_base + (uint32_t)cur * PS_SZ;
#pragma unroll
            for (int kh = 0; kh < 2; kh++) {
                uint32_t afr[2][4];
                LDSM4(afr[0], acur + kh * 32);                 // rows wM*32..+15
                LDSM4(afr[1], acur + kh * 32 + 16 * PPITCH_B); // rows +16..+31
                const int j   = kh * 16 + bj_lane;
                const uint32_t brow = hbase + j * 512;
                const uint32_t jx   = (uint32_t)(j & 7) << 4;
                uint32_t bfr[4][4];
#pragma unroll
                for (int nf = 0; nf < 4; nf++) {
                    int f = wF * 64 + nf * 16 + bf_off;
                    uint32_t boff = ((uint32_t)(f >> 3) << 4) ^ jx;
                    LDSM4T(bfr[nf], brow + boff);
                }
#pragma unroll
                for (int mf = 0; mf < 2; mf++)
#pragma unroll
                    for (int n8 = 0; n8 < 8; n8++)
                        MMA16816(acc[mf][n8], afr[mf],
                                 bfr[n8 >> 1][(n8 & 1) * 2],
                                 bfr[n8 >> 1][(n8 & 1) * 2 + 1]);
            }
        }
        __syncthreads();
    }

    // ---- Z reduction: threads sharing a row differ only in g ----
#pragma unroll
    for (int o = 1; o < 8; o <<= 1)
#pragma unroll
        for (int m = 0; m < 2; m++) zac[m] += __shfl_xor_sync(0xffffffffu, zac[m], o);
    float* zsh = (float*)(sm + ZSH_OFF);
    if (g == 0)
#pragma unroll
        for (int m = 0; m < 2; m++) zsh[r0 + 32 * m] = zac[m];
    __syncthreads();

    // ---- epilogue: divide by Z, elu, store ----
#pragma unroll
    for (int mf = 0; mf < 2; mf++) {
        const int ra = wM * 32 + mf * 16 + (lane >> 2);  // local row a
        const float rza = 1.0f / zsh[ra];
        const float rzb = 1.0f / zsh[ra + 8];
        float* orow_a = OUT + (size_t)(i0 + ra) * FEAT;
        float* orow_b = OUT + (size_t)(i0 + ra + 8) * FEAT;
#pragma unroll
        for (int n8 = 0; n8 < 8; n8++) {
            const int col = wF * 64 + n8 * 8 + (lane & 3) * 2;
            float v0 = acc[mf][n8][0] * rza, v1 = acc[mf][n8][1] * rza;
            float v2 = acc[mf][n8][2] * rzb, v3 = acc[mf][n8][3] * rzb;
            v0 = (v0 > 0.f) ? v0 : expm1f(v0);
            v1 = (v1 > 0.f) ? v1 : expm1f(v1);
            v2 = (v2 > 0.f) ? v2 : expm1f(v2);
            v3 = (v3 > 0.f) ? v3 : expm1f(v3);
            *(float2*)(orow_a + col) = make_float2(v0, v1);
            *(float2*)(orow_b + col) = make_float2(v2, v3);
        }
    }
}

// ---------------------------------------------------------------------------
extern "C" void kernel_launch(void* const* d_in, const int* in_sizes, int n_in,
                              void* d_out, int out_size) {
    (void)in_sizes; (void)n_in; (void)out_size;
    const float* X   = (const float*)d_in[0];   // input [8192,256] f32
    const int*   ADJ = (const int*)d_in[1];     // adj   [8192,8192] i32
    const float* W   = (const float*)d_in[2];   // W     [256,256] f32
    const float* A   = (const float*)d_in[3];   // a     [512,1]  f32
    float* OUT = (float*)d_out;                 // [8192,256] f32

    gemm_h_kernel<<<dim3(4, 128), 256>>>(X, W);
    spack_kernel<<<N_NODES / 8, 256>>>(A);
    cudaFuncSetAttribute(gat_mma_kernel,
                         cudaFuncAttributeMaxDynamicSharedMemorySize, SMEMM_BYTES);
    gat_mma_kernel<<<N_NODES / BM, THREADS, SMEMM_BYTES>>>(ADJ, OUT);
}

// round 10
// speedup vs baseline: 3.6144x; 1.1050x over previous
#include <cuda_runtime.h>
#include <cuda_fp16.h>
#include <cstdint>
#include <cstddef>

#define N_NODES 8192
#define FEAT    256
#define BM      64           // output rows per CTA (main kernel)
#define BK      32           // k-tile (nodes)
#define NTILES  (N_NODES / BK)   // 256
#define THREADS 256

// Scratch (no runtime allocation allowed)
__device__ float  d_H [N_NODES * FEAT];  // h = X@W (fp32 exact, for spack)
__device__ __half d_Hh[N_NODES * FEAT];  // h in fp16 (MMA B operand), row-major
__device__ float4 d_G1[N_NODES];         // (s1, exp(s1), exp(0.2 s1), 0)
__device__ float4 d_G2[N_NODES];         // (s2, exp(s2), exp(0.2 s2), 0)

// ---------------------------------------------------------------------------
// helpers
// ---------------------------------------------------------------------------
__device__ __forceinline__ uint32_t smem_u32(const void* p) {
    uint32_t a;
    asm("{ .reg .u64 t; cvta.to.shared.u64 t, %1; cvt.u32.u64 %0, t; }" : "=r"(a) : "l"(p));
    return a;
}
__device__ __forceinline__ void cp16(void* dst, const void* src) {
    unsigned d = (unsigned)__cvta_generic_to_shared(dst);
    asm volatile("cp.async.cg.shared.global [%0], [%1], 16;" :: "r"(d), "l"(src));
}
__device__ __forceinline__ void cp_commit() {
    asm volatile("cp.async.commit_group;" ::: "memory");
}
template <int N>
__device__ __forceinline__ void cp_wait() {
    asm volatile("cp.async.wait_group %0;" :: "n"(N) : "memory");
}
#define LDSM4(R, addr)                                                          \
    asm volatile("ldmatrix.sync.aligned.m8n8.x4.shared.b16 {%0,%1,%2,%3}, [%4];" \
                 : "=r"((R)[0]), "=r"((R)[1]), "=r"((R)[2]), "=r"((R)[3])       \
                 : "r"(addr))
#define LDSM4T(R, addr)                                                               \
    asm volatile("ldmatrix.sync.aligned.m8n8.x4.trans.shared.b16 {%0,%1,%2,%3}, [%4];" \
                 : "=r"((R)[0]), "=r"((R)[1]), "=r"((R)[2]), "=r"((R)[3])             \
                 : "r"(addr))
#define MMA16816(D, A, B0, B1)                                                  \
    asm volatile("mma.sync.aligned.m16n8k16.row.col.f32.f16.f16.f32 "           \
                 "{%0,%1,%2,%3}, {%4,%5,%6,%7}, {%8,%9}, {%0,%1,%2,%3};"        \
                 : "+f"((D)[0]), "+f"((D)[1]), "+f"((D)[2]), "+f"((D)[3])       \
                 : "r"((A)[0]), "r"((A)[1]), "r"((A)[2]), "r"((A)[3]),          \
                   "r"(B0), "r"(B1))

// ---------------------------------------------------------------------------
// Kernel 1: h = X @ W (fp32 exact) ; also d_Hh = fp16(h) row-major
// (unchanged from passing R9 kernel)
// ---------------------------------------------------------------------------
__global__ __launch_bounds__(256) void gemm_h_kernel(const float* __restrict__ X,
                                                     const float* __restrict__ W) {
    __shared__ float Xs[64][16];
    __shared__ float Ws[16][64];
    const int t  = threadIdx.x;
    const int tx = t & 15, ty = t >> 4;
    const int i0 = blockIdx.y * 64, j0 = blockIdx.x * 64;
    float acc[4][4] = {};
    for (int k0 = 0; k0 < FEAT; k0 += 16) {
        {
            int r = t >> 2, kq = (t & 3) * 4;
            *(float4*)&Xs[r][kq] = *(const float4*)(X + (size_t)(i0 + r) * FEAT + k0 + kq);
            int kk = t >> 4, jq = (t & 15) * 4;
            *(float4*)&Ws[kk][jq] = *(const float4*)(W + (size_t)(k0 + kk) * FEAT + j0 + jq);
        }
        __syncthreads();
#pragma unroll
        for (int k = 0; k < 16; k++) {
            float xv[4], wv[4];
#pragma unroll
            for (int p = 0; p < 4; p++) xv[p] = Xs[ty * 4 + p][k];
#pragma unroll
            for (int q = 0; q < 4; q++) wv[q] = Ws[k][tx * 4 + q];
#pragma unroll
            for (int p = 0; p < 4; p++)
#pragma unroll
                for (int q = 0; q < 4; q++) acc[p][q] = fmaf(xv[p], wv[q], acc[p][q]);
        }
        __syncthreads();
    }
#pragma unroll
    for (int p = 0; p < 4; p++) {
        float4 o = make_float4(acc[p][0], acc[p][1], acc[p][2], acc[p][3]);
        *(float4*)(d_H + (size_t)(i0 + ty * 4 + p) * FEAT + j0 + tx * 4) = o;
        __half2 h01 = __floats2half2_rn(acc[p][0], acc[p][1]);
        __half2 h23 = __floats2half2_rn(acc[p][2], acc[p][3]);
        uint2 hp;
        hp.x = *(uint32_t*)&h01;
        hp.y = *(uint32_t*)&h23;
        *(uint2*)(d_Hh + (size_t)(i0 + ty * 4 + p) * FEAT + j0 + tx * 4) = hp;
    }
}

// ---------------------------------------------------------------------------
// Kernel 2: s1/s2 + separable exp factors (unchanged).
// ---------------------------------------------------------------------------
__global__ __launch_bounds__(256) void spack_kernel(const float* __restrict__ A) {
    const int lane = threadIdx.x & 31;
    const int wid  = threadIdx.x >> 5;
    const int row  = blockIdx.x * 8 + wid;
    const float* hr = d_H + (size_t)row * FEAT;
    float s1 = 0.f, s2 = 0.f;
#pragma unroll
    for (int q = 0; q < 2; q++) {
        int f = lane * 8 + q * 4;
        float4 hv = *(const float4*)(hr + f);
        float4 a1 = *(const float4*)(A + f);
        float4 a2 = *(const float4*)(A + FEAT + f);
        s1 += hv.x * a1.x + hv.y * a1.y + hv.z * a1.z + hv.w * a1.w;
        s2 += hv.x * a2.x + hv.y * a2.y + hv.z * a2.z + hv.w * a2.w;
    }
#pragma unroll
    for (int o = 16; o > 0; o >>= 1) {
        s1 += __shfl_xor_sync(0xffffffffu, s1, o);
        s2 += __shfl_xor_sync(0xffffffffu, s2, o);
    }
    if (lane == 0) {
        d_G1[row] = make_float4(s1, expf(s1), expf(0.2f * s1), 0.f);
        d_G2[row] = make_float4(s2, expf(s2), expf(0.2f * s2), 0.f);
    }
}

// ---------------------------------------------------------------------------
// Kernel 3: flash-style fused masked-softmax @ h, fp16 mma.sync (HMMA).
// NEW: P-gen for tile s+1 overlaps with MMA for tile s; 1 syncthreads/tile;
//      warps 0-3 run genP->MMA, warps 4-7 run MMA->genP (per-SMSP phase mix).
// SMEM layout (dynamic):
//   Hs   : 2 x 16384  (H tile 32(j) x 256(f) fp16, 16B-chunk XOR swizzle) @ 0
//   adjs : 4 x 8192   (adj tile 64 x 32 i32, linear)                     @ 32768
//   Ps   : 2 x 5120   (P tile 64 x 32 fp16, row pitch 40 halves = 80B)   @ 65536
//   g2s  : 4 x 512    (32 float4)                                        @ 75776
//   zsh  : 64 floats                                                     @ 77824
#define HS_OFF   0
#define HS_SZ    16384
#define ADJ_OFF  32768
#define ADJ_SZ   8192
#define PS_OFF   65536
#define PS_SZ    5120
#define G2_OFF   75776
#define ZSH_OFF  77824
#define SMEMM_BYTES 78080
#define PPITCH_B 80     // P row pitch in bytes (40 halves)

__global__ __launch_bounds__(THREADS, 1) void gat_mma_kernel(const int* __restrict__ ADJ,
                                                             float* __restrict__ OUT) {
    extern __shared__ char sm[];
    const uint32_t smb = smem_u32(sm);
    const int t    = threadIdx.x;
    const int wid  = t >> 5, lane = t & 31;
    const int i0   = blockIdx.x * BM;
    const int g    = t & 7;       // P-gen: k-quad (cols 4g..4g+3)
    const int r0   = t >> 3;      // P-gen: row base (rows r0, r0+32)
    const int wM   = wid & 1;     // warp M tile: rows wM*32 .. +31
    const int wF   = wid >> 1;    // warp F tile: cols wF*64 .. +63

    float4 g1v[2];
#pragma unroll
    for (int m = 0; m < 2; m++) g1v[m] = d_G1[i0 + r0 + 32 * m];
    float zac[2] = {0.f, 0.f};

    float acc[2][8][4];           // [mfrag][n8frag][reg]
#pragma unroll
    for (int a = 0; a < 2; a++)
#pragma unroll
        for (int b = 0; b < 8; b++)
#pragma unroll
            for (int c = 0; c < 4; c++) acc[a][b][c] = 0.f;

    // ---- async loaders ----
    auto load_adj = [&](int s, int ab) {
        const int j0 = s * BK;
        char* adst = sm + ADJ_OFF + ab * ADJ_SZ;
#pragma unroll
        for (int m = 0; m < 2; m++) {
            int e = t + 256 * m;
            int r = e >> 3, c = e & 7;
            cp16(adst + r * 128 + c * 16, ADJ + (size_t)(i0 + r) * N_NODES + j0 + c * 4);
        }
        if (t < 32) cp16(sm + G2_OFF + ab * 512 + t * 16, d_G2 + j0 + t);
    };
    auto load_h = [&](int s, int hb) {
        const int j0 = s * BK;
        char* hdst = sm + HS_OFF + hb * HS_SZ;
#pragma unroll
        for (int m = 0; m < 4; m++) {
            int e = t + 256 * m;
            int j = e >> 5, c = e & 31;
            cp16(hdst + j * 512 + ((c ^ (j & 7)) << 4),
                 d_Hh + (size_t)(j0 + j) * FEAT + c * 8);
        }
    };

    // ---- P-tile generation for tile sn: w = adj ? exp(lrelu(s1+s2)) : 0 ----
    auto do_genp = [&](int sn) {
        const int ab = sn & 3, pb = sn & 1;
        const float4* g2b = (const float4*)(sm + G2_OFF + ab * 512) + g * 4;
        float4 G[4];
#pragma unroll
        for (int j = 0; j < 4; j++) G[j] = g2b[j];
        const int4* abase = (const int4*)(sm + ADJ_OFF + ab * ADJ_SZ);
        char* pbase = sm + PS_OFF + pb * PS_SZ;
#pragma unroll
        for (int m = 0; m < 2; m++) {
            const int r = r0 + 32 * m;
            int4 av = abase[r * 8 + g];
            int msk[4] = {av.x, av.y, av.z, av.w};
            __half hw[4];
#pragma unroll
            for (int j = 0; j < 4; j++) {
                float x = g1v[m].x + G[j].x;
                float e = (x >= 0.f ? g1v[m].y : g1v[m].z) *
                          (x >= 0.f ? G[j].y : G[j].z);
                e = (msk[j] != 0) ? e : 0.f;
                hw[j] = __float2half_rn(e);
                zac[m] += __half2float(hw[j]);   // Z from the SAME rounded w
            }
            __half2 p01 = __halves2half2(hw[0], hw[1]);
            __half2 p23 = __halves2half2(hw[2], hw[3]);
            uint2 pk;
            pk.x = *(uint32_t*)&p01;
            pk.y = *(uint32_t*)&p23;
            *(uint2*)(pbase + r * PPITCH_B + g * 8) = pk;
        }
    };

    // precomputed ldmatrix address pieces
    const uint32_t a_base = smb + PS_OFF +
                            (uint32_t)(wM * 32 + (lane & 15)) * PPITCH_B +
                            (uint32_t)((lane >> 4) * 8) * 2;
    const int bj_lane = lane & 15;           // row within k-half
    const int bf_off  = (lane >> 4) * 8;     // col offset within n16

    // ---- HMMA for tile s: acc += P[64x32] @ H[32x256] (warp tile 32x64) ----
    auto do_mma = [&](int s) {
        const int cur = s & 1;
        const uint32_t hbase = smb + HS_OFF + cur * HS_SZ;
        const uint32_t acur  = a_base + (uint32_t)cur * PS_SZ;
#pragma unroll
        for (int kh = 0; kh < 2; kh++) {
            uint32_t afr[2][4];
            LDSM4(afr[0], acur + kh * 32);                 // rows wM*32..+15
            LDSM4(afr[1], acur + kh * 32 + 16 * PPITCH_B); // rows +16..+31
            const int j   = kh * 16 + bj_lane;
            const uint32_t brow = hbase + j * 512;
            const uint32_t jx   = (uint32_t)(j & 7) << 4;
            uint32_t bfr[4][4];
#pragma unroll
            for (int nf = 0; nf < 4; nf++) {
                int f = wF * 64 + nf * 16 + bf_off;
                uint32_t boff = ((uint32_t)(f >> 3) << 4) ^ jx;
                LDSM4T(bfr[nf], brow + boff);
            }
#pragma unroll
            for (int mf = 0; mf < 2; mf++)
#pragma unroll
                for (int n8 = 0; n8 < 8; n8++)
                    MMA16816(acc[mf][n8], afr[mf],
                             bfr[n8 >> 1][(n8 & 1) * 2],
                             bfr[n8 >> 1][(n8 & 1) * 2 + 1]);
        }
    };

    // ---- prologue: adj[0] | adj[1]+H[0] in flight; gen P[0] ----
    load_adj(0, 0);
    cp_commit();
    load_adj(1, 1);
    load_h(0, 0);
    cp_commit();
    cp_wait<1>();          // adj[0], g2[0] resident
    __syncthreads();
    do_genp(0);
    __syncthreads();

    // ---- main loop: one sync per tile; genP(s+1) overlapped with MMA(s) ----
    for (int s = 0; s < NTILES; ++s) {
        if (s + 1 < NTILES) {
            load_h(s + 1, (s + 1) & 1);
            if (s + 2 < NTILES) load_adj(s + 2, (s + 2) & 3);
            cp_commit();
            cp_wait<1>();  // H[s], adj[s+1], g2[s+1] resident
        } else {
            cp_wait<0>();
        }
        // phase-staggered: each SMSP gets one ALU-first and one MMA-first warp
        if ((wid & 4) == 0) {
            if (s + 1 < NTILES) do_genp(s + 1);
            do_mma(s);
        } else {
            do_mma(s);
            if (s + 1 < NTILES) do_genp(s + 1);
        }
        __syncthreads();
    }

    // ---- Z reduction: threads sharing a row differ only in g ----
#pragma unroll
    for (int o = 1; o < 8; o <<= 1)
#pragma unroll
        for (int m = 0; m < 2; m++) zac[m] += __shfl_xor_sync(0xffffffffu, zac[m], o);
    float* zsh = (float*)(sm + ZSH_OFF);
    if (g == 0)
#pragma unroll
        for (int m = 0; m < 2; m++) zsh[r0 + 32 * m] = zac[m];
    __syncthreads();

    // ---- epilogue: divide by Z, elu, store ----
#pragma unroll
    for (int mf = 0; mf < 2; mf++) {
        const int ra = wM * 32 + mf * 16 + (lane >> 2);  // local row a
        const float rza = 1.0f / zsh[ra];
        const float rzb = 1.0f / zsh[ra + 8];
        float* orow_a = OUT + (size_t)(i0 + ra) * FEAT;
        float* orow_b = OUT + (size_t)(i0 + ra + 8) * FEAT;
#pragma unroll
        for (int n8 = 0; n8 < 8; n8++) {
            const int col = wF * 64 + n8 * 8 + (lane & 3) * 2;
            float v0 = acc[mf][n8][0] * rza, v1 = acc[mf][n8][1] * rza;
            float v2 = acc[mf][n8][2] * rzb, v3 = acc[mf][n8][3] * rzb;
            v0 = (v0 > 0.f) ? v0 : expm1f(v0);
            v1 = (v1 > 0.f) ? v1 : expm1f(v1);
            v2 = (v2 > 0.f) ? v2 : expm1f(v2);
            v3 = (v3 > 0.f) ? v3 : expm1f(v3);
            *(float2*)(orow_a + col) = make_float2(v0, v1);
            *(float2*)(orow_b + col) = make_float2(v2, v3);
        }
    }
}

// ---------------------------------------------------------------------------
extern "C" void kernel_launch(void* const* d_in, const int* in_sizes, int n_in,
                              void* d_out, int out_size) {
    (void)in_sizes; (void)n_in; (void)out_size;
    const float* X   = (const float*)d_in[0];   // input [8192,256] f32
    const int*   ADJ = (const int*)d_in[1];     // adj   [8192,8192] i32
    const float* W   = (const float*)d_in[2];   // W     [256,256] f32
    const float* A   = (const float*)d_in[3];   // a     [512,1]  f32
    float* OUT = (float*)d_out;                 // [8192,256] f32

    gemm_h_kernel<<<dim3(4, 128), 256>>>(X, W);
    spack_kernel<<<N_NODES / 8, 256>>>(A);
    cudaFuncSetAttribute(gat_mma_kernel,
                         cudaFuncAttributeMaxDynamicSharedMemorySize, SMEMM_BYTES);
    gat_mma_kernel<<<N_NODES / BM, THREADS, SMEMM_BYTES>>>(ADJ, OUT);
}